// round 7
// baseline (speedup 1.0000x reference)
#include <cuda_runtime.h>

// OpponentModelOracle: B=4096 batches, H=W=64, C=8.
// One CTA per batch (grid=4096, dynamic scheduling). 1024 threads/CTA at
// occ 2: same threads/SM as 512@occ4, but each CTA owns half an SM, so
// per-CTA duration halves again -> end-of-grid DRAM demand ramp halves.
// Thread t owns cells {t + k*1024 : k=0..3}. Single LDG.128 read pass
// (channels 0..3 per cell), register/shared reductions, coalesced writes.

#define HW    4096
#define WDIM  64
#define NTHR  1024
#define KIT   4     // HW / NTHR
#define NWARP 32

__global__ void __launch_bounds__(NTHR, 2)
oracle_kernel(const float4* __restrict__ x4,
              const float*  __restrict__ opp_start,
              float*        __restrict__ out)
{
    __shared__ int s_food[NWARP], s_opp[NWARP], s_first[NWARP];
    __shared__ int s_k1[NWARP], s_v2[NWARP];

    const int t    = threadIdx.x;
    const int warp = t >> 5;
    const int lane = t & 31;
    const long long b = blockIdx.x;

    const float4* xb = x4 + b * (long long)(HW * 2);   // 2 float4 per cell

    // ---------------- Phase 1: masks + counts + first opponent -------------
    int foodbits = 0;            // bit k: cell t + k*1024 is food
    int cfood = 0, copp = 0;
    int firstopp = 0x7FFFFFFF;

    #pragma unroll
    for (int k = 0; k < KIT; k++) {
        const int cell = t + (k << 10);
        float4 v = __ldg(&xb[(long long)cell * 2]);    // channels 0..3
        const int food = (v.y == 1.0f);
        const int opp  = (v.w == 1.0f);
        foodbits |= food << k;
        cfood += food;
        copp  += opp;
        if (opp && cell < firstopp) firstopp = cell;
    }

    #pragma unroll
    for (int o = 16; o; o >>= 1) {
        cfood    += __shfl_down_sync(0xFFFFFFFFu, cfood, o);
        copp     += __shfl_down_sync(0xFFFFFFFFu, copp, o);
        int f     = __shfl_down_sync(0xFFFFFFFFu, firstopp, o);
        if (f < firstopp) firstopp = f;
    }
    if (lane == 0) { s_food[warp] = cfood; s_opp[warp] = copp; s_first[warp] = firstopp; }
    __syncthreads();

    int n_food = 0, n_opp = 0, first = 0x7FFFFFFF;
    #pragma unroll
    for (int i = 0; i < NWARP; i++) {
        n_food += s_food[i];
        n_opp  += s_opp[i];
        if (s_first[i] < first) first = s_first[i];
    }
    if (first == 0x7FFFFFFF) first = 0;   // jnp.argmax(all-false) == 0
    const int orow = first >> 6;
    const int ocol = first & (WDIM - 1);

    // ---------------- Phase 2: two smallest distances over food cells ------
    // key = (dsq << 12) | idx  -> lexicographic (distance, row-major idx) min,
    // matching argmin-first-occurrence semantics. dsq <= 7938 < 2^13.
    int k1 = 0x7FFFFFFF;   // packed best
    int v2 = 0x7FFFFFFF;   // second-best dsq (min over all but argmin element)

    #pragma unroll
    for (int k = 0; k < KIT; k++) {
        if ((foodbits >> k) & 1) {
            const int cell = t + (k << 10);
            const int dr = (cell >> 6) - orow;
            const int dc = (cell & (WDIM - 1)) - ocol;
            const int dsq = dr * dr + dc * dc;
            const int key = (dsq << 12) | cell;
            if (key < k1) { const int old = k1 >> 12; if (old < v2) v2 = old; k1 = key; }
            else          { if (dsq < v2) v2 = dsq; }
        }
    }
    #pragma unroll
    for (int o = 16; o; o >>= 1) {
        const int ok1 = __shfl_down_sync(0xFFFFFFFFu, k1, o);
        const int ov2 = __shfl_down_sync(0xFFFFFFFFu, v2, o);
        if (ov2 < v2) v2 = ov2;
        if (ok1 < k1) { const int old = k1 >> 12; if (old < v2) v2 = old; k1 = ok1; }
        else          { const int od  = ok1 >> 12; if (od  < v2) v2 = od; }
    }
    if (lane == 0) { s_k1[warp] = k1; s_v2[warp] = v2; }
    __syncthreads();

    k1 = 0x7FFFFFFF; v2 = 0x7FFFFFFF;
    #pragma unroll
    for (int i = 0; i < NWARP; i++) {
        const int ok1 = s_k1[i], ov2 = s_v2[i];
        if (ov2 < v2) v2 = ov2;
        if (ok1 < k1) { const int old = k1 >> 12; if (old < v2) v2 = old; k1 = ok1; }
        else          { const int od  = ok1 >> 12; if (od  < v2) v2 = od; }
    }

    // ---------------- Branch flags (computed redundantly by all threads) ---
    const float min1 = __fsqrt_rn((float)(k1 >> 12));
    const float min2 = __fsqrt_rn((float)v2);
    const float diff = min2 - min1;
    const int   min_idx = k1 & (HW - 1);

    const float os0 = __ldg(&opp_start[0]);
    const float os1 = __ldg(&opp_start[1]);
    const bool matches   = ((float)orow == os0) && ((float)ocol == os1);
    const bool branchA   = (n_food > 1) && (n_opp > 0) && !matches;
    const bool ambiguous = (branchA && (diff < 0.1f)) || ((n_food > 1) && !branchA);
    const bool pick      = (branchA && (diff >= 0.1f)) || (n_food == 1);

    // ---------------- Phase 3: coalesced write -----------------------------
    float* ob = out + b * (long long)HW;
    #pragma unroll
    for (int k = 0; k < KIT; k++) {
        const int cell = t + (k << 10);
        const int food = (foodbits >> k) & 1;
        int hit;
        if (ambiguous)      hit = food;
        else if (pick)      hit = (cell == min_idx);
        else                hit = 0;
        ob[cell] = hit ? 10.0f : -10.0f;
    }
}

extern "C" void kernel_launch(void* const* d_in, const int* in_sizes, int n_in,
                              void* d_out, int out_size)
{
    // metadata order: x [B,H,W,C] f32, opp_start [2] f32 — disambiguate by size.
    int xi = 0, si = 1;
    if (n_in >= 2 && in_sizes[0] <= 2) { xi = 1; si = 0; }
    const float4* x   = (const float4*)d_in[xi];
    const float*  ops = (const float*)d_in[si];
    float* out = (float*)d_out;

    oracle_kernel<<<4096, NTHR>>>(x, ops, out);
}

// round 8
// speedup vs baseline: 1.2055x; 1.2055x over previous
#include <cuda_runtime.h>

// OpponentModelOracle: B=4096 batches, H=W=64, C=8.
// R5 config (best: 93.0us) + streaming cache hints as the single change.
// One CTA per batch (grid=4096, dynamic scheduling). 512 threads/CTA, occ 4,
// KIT=8 (per-thread MLP=8 — R6 showed MLP=4 starves DRAM).
// Thread t owns cells {t + k*512 : k=0..7}. Single LDG.128.CS read pass
// (channels 0..3 per cell), register/shared reductions, STG.CS write pass.

#define HW    4096
#define WDIM  64
#define NTHR  512
#define KIT   8     // HW / NTHR
#define NWARP 16

__global__ void __launch_bounds__(NTHR, 4)
oracle_kernel(const float4* __restrict__ x4,
              const float*  __restrict__ opp_start,
              float*        __restrict__ out)
{
    __shared__ int s_food[NWARP], s_opp[NWARP], s_first[NWARP];
    __shared__ int s_k1[NWARP], s_v2[NWARP];

    const int t    = threadIdx.x;
    const int warp = t >> 5;
    const int lane = t & 31;
    const long long b = blockIdx.x;

    const float4* xb = x4 + b * (long long)(HW * 2);   // 2 float4 per cell

    // ---------------- Phase 1: masks + counts + first opponent -------------
    int foodbits = 0;            // bit k: cell t + k*512 is food
    int cfood = 0, copp = 0;
    int firstopp = 0x7FFFFFFF;

    #pragma unroll
    for (int k = 0; k < KIT; k++) {
        const int cell = t + (k << 9);
        float4 v = __ldcs(&xb[(long long)cell * 2]);   // streaming: ch 0..3
        const int food = (v.y == 1.0f);
        const int opp  = (v.w == 1.0f);
        foodbits |= food << k;
        cfood += food;
        copp  += opp;
        if (opp && cell < firstopp) firstopp = cell;
    }

    #pragma unroll
    for (int o = 16; o; o >>= 1) {
        cfood    += __shfl_down_sync(0xFFFFFFFFu, cfood, o);
        copp     += __shfl_down_sync(0xFFFFFFFFu, copp, o);
        int f     = __shfl_down_sync(0xFFFFFFFFu, firstopp, o);
        if (f < firstopp) firstopp = f;
    }
    if (lane == 0) { s_food[warp] = cfood; s_opp[warp] = copp; s_first[warp] = firstopp; }
    __syncthreads();

    int n_food = 0, n_opp = 0, first = 0x7FFFFFFF;
    #pragma unroll
    for (int i = 0; i < NWARP; i++) {
        n_food += s_food[i];
        n_opp  += s_opp[i];
        if (s_first[i] < first) first = s_first[i];
    }
    if (first == 0x7FFFFFFF) first = 0;   // jnp.argmax(all-false) == 0
    const int orow = first >> 6;
    const int ocol = first & (WDIM - 1);

    // ---------------- Phase 2: two smallest distances over food cells ------
    // key = (dsq << 12) | idx  -> lexicographic (distance, row-major idx) min,
    // matching argmin-first-occurrence semantics. dsq <= 7938 < 2^13.
    int k1 = 0x7FFFFFFF;   // packed best
    int v2 = 0x7FFFFFFF;   // second-best dsq (min over all but argmin element)

    #pragma unroll
    for (int k = 0; k < KIT; k++) {
        if ((foodbits >> k) & 1) {
            const int cell = t + (k << 9);
            const int dr = (cell >> 6) - orow;
            const int dc = (cell & (WDIM - 1)) - ocol;
            const int dsq = dr * dr + dc * dc;
            const int key = (dsq << 12) | cell;
            if (key < k1) { const int old = k1 >> 12; if (old < v2) v2 = old; k1 = key; }
            else          { if (dsq < v2) v2 = dsq; }
        }
    }
    #pragma unroll
    for (int o = 16; o; o >>= 1) {
        const int ok1 = __shfl_down_sync(0xFFFFFFFFu, k1, o);
        const int ov2 = __shfl_down_sync(0xFFFFFFFFu, v2, o);
        if (ov2 < v2) v2 = ov2;
        if (ok1 < k1) { const int old = k1 >> 12; if (old < v2) v2 = old; k1 = ok1; }
        else          { const int od  = ok1 >> 12; if (od  < v2) v2 = od; }
    }
    if (lane == 0) { s_k1[warp] = k1; s_v2[warp] = v2; }
    __syncthreads();

    k1 = 0x7FFFFFFF; v2 = 0x7FFFFFFF;
    #pragma unroll
    for (int i = 0; i < NWARP; i++) {
        const int ok1 = s_k1[i], ov2 = s_v2[i];
        if (ov2 < v2) v2 = ov2;
        if (ok1 < k1) { const int old = k1 >> 12; if (old < v2) v2 = old; k1 = ok1; }
        else          { const int od  = ok1 >> 12; if (od  < v2) v2 = od; }
    }

    // ---------------- Branch flags (computed redundantly by all threads) ---
    const float min1 = __fsqrt_rn((float)(k1 >> 12));
    const float min2 = __fsqrt_rn((float)v2);
    const float diff = min2 - min1;
    const int   min_idx = k1 & (HW - 1);

    const float os0 = __ldg(&opp_start[0]);
    const float os1 = __ldg(&opp_start[1]);
    const bool matches   = ((float)orow == os0) && ((float)ocol == os1);
    const bool branchA   = (n_food > 1) && (n_opp > 0) && !matches;
    const bool ambiguous = (branchA && (diff < 0.1f)) || ((n_food > 1) && !branchA);
    const bool pick      = (branchA && (diff >= 0.1f)) || (n_food == 1);

    // ---------------- Phase 3: streaming coalesced write -------------------
    float* ob = out + b * (long long)HW;
    #pragma unroll
    for (int k = 0; k < KIT; k++) {
        const int cell = t + (k << 9);
        const int food = (foodbits >> k) & 1;
        int hit;
        if (ambiguous)      hit = food;
        else if (pick)      hit = (cell == min_idx);
        else                hit = 0;
        __stcs(&ob[cell], hit ? 10.0f : -10.0f);
    }
}

extern "C" void kernel_launch(void* const* d_in, const int* in_sizes, int n_in,
                              void* d_out, int out_size)
{
    // metadata order: x [B,H,W,C] f32, opp_start [2] f32 — disambiguate by size.
    int xi = 0, si = 1;
    if (n_in >= 2 && in_sizes[0] <= 2) { xi = 1; si = 0; }
    const float4* x   = (const float4*)d_in[xi];
    const float*  ops = (const float*)d_in[si];
    float* out = (float*)d_out;

    oracle_kernel<<<4096, NTHR>>>(x, ops, out);
}